// round 2
// baseline (speedup 1.0000x reference)
#include <cuda_runtime.h>
#include <cstdint>
#include <cstddef>

// Problem constants
#define NB   64
#define NS   512
#define NUNI 1024
#define NH   1024
#define NFLD 256
#define ROWS (NB * NS)           // 32768
#define EMIT_ELEMS ((size_t)NB * NS * NH)   // 33554432

// ---------------- scratch (static __device__: no allocation) ----------------
__device__ float g_pre[(size_t)ROWS * 4 * NH];   // 32768 x 4096  (x@Wx + bW)
__device__ float g_fg [(size_t)ROWS * 2 * NH];   // 32768 x 2048  (field gates)
__device__ float g_ft [(size_t)ROWS * NH];       // 32768 x 1024  (field term)
__device__ float g_h0[NB * NH];
__device__ float g_h1[NB * NH];
__device__ float g_c0[NB * NH];
__device__ float g_c1[NB * NH];

// ---------------- helpers ----------------
__device__ __forceinline__ uint32_t f2tf32(float x) {
    uint32_t r;
    asm("cvt.rna.tf32.f32 %0, %1;" : "=r"(r) : "f"(x));
    return r;
}

__device__ __forceinline__ void mma_tf32(float d[4], const uint32_t a[4], const uint32_t b[2]) {
    asm volatile(
        "mma.sync.aligned.m16n8k8.row.col.f32.tf32.tf32.f32 "
        "{%0,%1,%2,%3}, {%4,%5,%6,%7}, {%8,%9}, {%0,%1,%2,%3};"
        : "+f"(d[0]), "+f"(d[1]), "+f"(d[2]), "+f"(d[3])
        : "r"(a[0]), "r"(a[1]), "r"(a[2]), "r"(a[3]), "r"(b[0]), "r"(b[1]));
}

__device__ __forceinline__ float sigf(float x) { return 1.0f / (1.0f + expf(-x)); }

// ---------------- generic tf32 GEMM: C = A(MxK) * B(KxN) + bias ----------------
// BM=128, BN=128, BK=32, 256 threads (8 warps: 4x2), warp tile 32x64.
#define BM 128
#define BN 128
#define BK 32

__global__ __launch_bounds__(256) void gemm_tf32_kernel(
    const float* __restrict__ A, const float* __restrict__ B,
    const float* __restrict__ bias, float* __restrict__ C,
    int K, int lda, int ldb, int ldc)
{
    __shared__ float As[BM][BK + 8];   // row stride 40 floats (160B, 16B aligned)
    __shared__ float Bs[BK][BN + 8];   // row stride 136 floats (544B, 16B aligned)

    const int tid  = threadIdx.x;
    const int warp = tid >> 5, lane = tid & 31;
    const int wm = warp >> 1, wn = warp & 1;       // 4 x 2 warps
    const int gid = lane >> 2, kid = lane & 3;
    const int m0 = blockIdx.y * BM;
    const int n0 = blockIdx.x * BN;

    float acc[2][8][4];
    #pragma unroll
    for (int i = 0; i < 2; i++)
        #pragma unroll
        for (int j = 0; j < 8; j++)
            #pragma unroll
            for (int q = 0; q < 4; q++) acc[i][j][q] = 0.0f;

    for (int kt = 0; kt < K; kt += BK) {
        // Load A tile 128x32 (1024 float4, 4 per thread)
        #pragma unroll
        for (int i = 0; i < 4; i++) {
            int idx = tid + i * 256;
            int r = idx >> 3, q = idx & 7;
            float4 v = *(const float4*)(A + (size_t)(m0 + r) * lda + kt + q * 4);
            *(float4*)&As[r][q * 4] = v;
        }
        // Load B tile 32x128 (1024 float4, 4 per thread)
        #pragma unroll
        for (int i = 0; i < 4; i++) {
            int idx = tid + i * 256;
            int r = idx >> 5, q = idx & 31;
            float4 v = *(const float4*)(B + (size_t)(kt + r) * ldb + n0 + q * 4);
            *(float4*)&Bs[r][q * 4] = v;
        }
        __syncthreads();

        #pragma unroll
        for (int kk = 0; kk < BK; kk += 8) {
            uint32_t af[2][4], bf[8][2];
            #pragma unroll
            for (int mi = 0; mi < 2; mi++) {
                int r = wm * 32 + mi * 16 + gid;
                af[mi][0] = f2tf32(As[r    ][kk + kid    ]);
                af[mi][1] = f2tf32(As[r + 8][kk + kid    ]);
                af[mi][2] = f2tf32(As[r    ][kk + kid + 4]);
                af[mi][3] = f2tf32(As[r + 8][kk + kid + 4]);
            }
            #pragma unroll
            for (int ni = 0; ni < 8; ni++) {
                int cc = wn * 64 + ni * 8 + gid;
                bf[ni][0] = f2tf32(Bs[kk + kid    ][cc]);
                bf[ni][1] = f2tf32(Bs[kk + kid + 4][cc]);
            }
            #pragma unroll
            for (int mi = 0; mi < 2; mi++)
                #pragma unroll
                for (int ni = 0; ni < 8; ni++)
                    mma_tf32(acc[mi][ni], af[mi], bf[ni]);
        }
        __syncthreads();
    }

    // Epilogue: add bias, store fp32
    #pragma unroll
    for (int mi = 0; mi < 2; mi++) {
        int r = m0 + wm * 32 + mi * 16 + gid;
        #pragma unroll
        for (int ni = 0; ni < 8; ni++) {
            int cc = n0 + wn * 64 + ni * 8 + 2 * kid;
            float b0 = bias[cc], b1 = bias[cc + 1];
            C[(size_t)r * ldc + cc]           = acc[mi][ni][0] + b0;
            C[(size_t)r * ldc + cc + 1]       = acc[mi][ni][1] + b1;
            C[(size_t)(r + 8) * ldc + cc]     = acc[mi][ni][2] + b0;
            C[(size_t)(r + 8) * ldc + cc + 1] = acc[mi][ni][3] + b1;
        }
    }
}

// ---------------- field activation: ft = sigmoid(r)*tanh(d) ----------------
__global__ void field_act_kernel(int total) {
    int i = blockIdx.x * blockDim.x + threadIdx.x;
    if (i >= total) return;
    int r = i >> 10, j = i & 1023;
    float rv = g_fg[(size_t)r * 2048 + j];
    float dv = g_fg[(size_t)r * 2048 + 1024 + j];
    g_ft[i] = sigf(rv) * tanhf(dv);
}

// ---------------- init / finalize ----------------
__global__ void zero_hc_kernel() {
    int i = blockIdx.x * blockDim.x + threadIdx.x;
    if (i < NB * NH) { g_h0[i] = 0.0f; g_c0[i] = 0.0f; }
}

__global__ void copy_hc_kernel(float* __restrict__ out_tail) {
    int i = blockIdx.x * blockDim.x + threadIdx.x;
    if (i < NB * NH) {
        out_tail[i]           = g_h0[i];   // after 512 steps, finals live in buffer 0
        out_tail[NB * NH + i] = g_c0[i];
    }
}

// ---------------- fused LSTM step: gates = pre[:,t,:] + h @ W_h; cell update ----------------
// Grid: (64 col-chunks of 16 h-cols, 2 batch halves). 256 threads, 8 warps.
// warp = (wm in 0..1 over 16-batch rows) x (wg in 0..3 over gate groups i/j/f/o).
__global__ __launch_bounds__(256) void lstm_step_kernel(
    const float* __restrict__ W,     // (2048, 4096); rows 1024.. are W_h
    const int*   __restrict__ len,
    float* __restrict__ out_emit,
    const float* __restrict__ hr, float* __restrict__ hw,
    const float* __restrict__ cr, float* __restrict__ cw,
    int t)
{
    __shared__ float As[32][BK + 8];   // h slice: 32 batches x 32 k
    __shared__ float Bs[BK][64 + 8];   // W_h slice: 32 k x 64 gate cols
    __shared__ float Gs[32][68];       // gate exchange: 32 batches x 64 cols

    const int tid  = threadIdx.x;
    const int warp = tid >> 5, lane = tid & 31;
    const int wm = warp >> 2, wg = warp & 3;
    const int gid = lane >> 2, kid = lane & 3;
    const int nc = blockIdx.x;   // h-col chunk (16 cols)
    const int bm = blockIdx.y;   // batch half
    const float* Wh = W + (size_t)1024 * 4096;

    float acc[2][4] = {{0.f,0.f,0.f,0.f},{0.f,0.f,0.f,0.f}};

    for (int kt = 0; kt < NH; kt += BK) {
        // h slice: 32 rows x 8 float4 = 256 loads, one per thread
        {
            int r = tid >> 3, q = tid & 7;
            *(float4*)&As[r][q * 4] =
                *(const float4*)(hr + (size_t)(bm * 32 + r) * NH + kt + q * 4);
        }
        // W_h slice: 32 rows x (4 gate groups x 4 float4) = 512 loads, 2 per thread
        #pragma unroll
        for (int i = 0; i < 2; i++) {
            int idx = tid + i * 256;
            int r = idx >> 4; int rem = idx & 15; int g = rem >> 2, q = rem & 3;
            *(float4*)&Bs[r][g * 16 + q * 4] =
                *(const float4*)(Wh + (size_t)(kt + r) * 4096 + g * 1024 + nc * 16 + q * 4);
        }
        __syncthreads();

        #pragma unroll
        for (int kk = 0; kk < BK; kk += 8) {
            uint32_t af[4], bf[2][2];
            int r = wm * 16 + gid;
            af[0] = f2tf32(As[r    ][kk + kid    ]);
            af[1] = f2tf32(As[r + 8][kk + kid    ]);
            af[2] = f2tf32(As[r    ][kk + kid + 4]);
            af[3] = f2tf32(As[r + 8][kk + kid + 4]);
            #pragma unroll
            for (int ni = 0; ni < 2; ni++) {
                int cc = wg * 16 + ni * 8 + gid;
                bf[ni][0] = f2tf32(Bs[kk + kid    ][cc]);
                bf[ni][1] = f2tf32(Bs[kk + kid + 4][cc]);
                mma_tf32(acc[ni], af, bf[ni]);
            }
        }
        __syncthreads();
    }

    // Dump accumulators to shared for cross-warp gate exchange
    #pragma unroll
    for (int ni = 0; ni < 2; ni++) {
        int r = wm * 16 + gid;
        int cc = wg * 16 + ni * 8 + 2 * kid;
        Gs[r    ][cc]     = acc[ni][0];
        Gs[r    ][cc + 1] = acc[ni][1];
        Gs[r + 8][cc]     = acc[ni][2];
        Gs[r + 8][cc + 1] = acc[ni][3];
    }
    __syncthreads();

    // Cell update: 32 batches x 16 h-cols = 512 cells, 2 per thread
    #pragma unroll
    for (int i = 0; i < 2; i++) {
        int idx = tid + i * 256;
        int lb = idx >> 4, cc = idx & 15;
        int b = bm * 32 + lb;
        int hcol = nc * 16 + cc;
        size_t prerow = ((size_t)b * NS + t) * 4096;
        float gi = Gs[lb][cc]      + g_pre[prerow + 0 * 1024 + hcol];
        float gj = Gs[lb][16 + cc] + g_pre[prerow + 1 * 1024 + hcol];
        float gf = Gs[lb][32 + cc] + g_pre[prerow + 2 * 1024 + hcol];
        float go = Gs[lb][48 + cc] + g_pre[prerow + 3 * 1024 + hcol];

        float c_old = cr[b * NH + hcol];
        float h_old = hr[b * NH + hcol];
        float fterm = g_ft[((size_t)b * NS + t) * NH + hcol];

        float c_new = sigf(gf + 1.0f) * c_old + sigf(gi) * tanhf(gj) + fterm;
        float h_new = sigf(go) * tanhf(c_new);

        bool act = (t < len[b]);
        out_emit[((size_t)b * NS + t) * NH + hcol] = act ? h_new : 0.0f;
        hw[b * NH + hcol] = act ? h_new : h_old;
        cw[b * NH + hcol] = act ? c_new : c_old;
    }
}

// ---------------- host ----------------
extern "C" void kernel_launch(void* const* d_in, const int* in_sizes, int n_in,
                              void* d_out, int out_size)
{
    const float* X   = (const float*)d_in[0];  // (64, 512, 1024)
    const float* F   = (const float*)d_in[1];  // (64, 512, 256)
    const int*   len = (const int*)  d_in[2];  // (64,)
    const float* W   = (const float*)d_in[3];  // (2048, 4096)
    const float* bW  = (const float*)d_in[4];  // (4096,)
    const float* W1  = (const float*)d_in[5];  // (256, 2048)
    const float* bW1 = (const float*)d_in[6];  // (2048,)
    float* out = (float*)d_out;

    float *pre_p, *fg_p, *h0_p, *h1_p, *c0_p, *c1_p;
    cudaGetSymbolAddress((void**)&pre_p, g_pre);
    cudaGetSymbolAddress((void**)&fg_p,  g_fg);
    cudaGetSymbolAddress((void**)&h0_p,  g_h0);
    cudaGetSymbolAddress((void**)&h1_p,  g_h1);
    cudaGetSymbolAddress((void**)&c0_p,  g_c0);
    cudaGetSymbolAddress((void**)&c1_p,  g_c1);

    // h0/c0 = 0
    zero_hc_kernel<<<(NB * NH + 255) / 256, 256>>>();

    // pre = X @ W[0:1024,:] + bW   (32768 x 4096, K=1024)
    gemm_tf32_kernel<<<dim3(4 * NH / BN, ROWS / BM), 256>>>(
        X, W, bW, pre_p, NUNI, NUNI, 4 * NH, 4 * NH);

    // fg = F @ W1 + bW1            (32768 x 2048, K=256)
    gemm_tf32_kernel<<<dim3(2 * NH / BN, ROWS / BM), 256>>>(
        F, W1, bW1, fg_p, NFLD, NFLD, 2 * NH, 2 * NH);

    // field term
    field_act_kernel<<<(int)((EMIT_ELEMS + 255) / 256), 256>>>((int)EMIT_ELEMS);

    // recurrence: 512 sequential fused steps, h/c double-buffered
    for (int t = 0; t < NS; t++) {
        const float* hr = (t & 1) ? h1_p : h0_p;
        float*       hw = (t & 1) ? h0_p : h1_p;
        const float* cr = (t & 1) ? c1_p : c0_p;
        float*       cw = (t & 1) ? c0_p : c1_p;
        lstm_step_kernel<<<dim3(64, 2), 256>>>(W, len, out, hr, hw, cr, cw, t);
    }

    // finals: after t=511 the write buffer was 0
    copy_hc_kernel<<<(NB * NH + 255) / 256, 256>>>(out + EMIT_ELEMS);
}

// round 3
// speedup vs baseline: 1.2899x; 1.2899x over previous
#include <cuda_runtime.h>
#include <cstdint>
#include <cstddef>

// Problem constants
#define NB   64
#define NS   512
#define NUNI 1024
#define NH   1024
#define NFLD 256
#define ROWS (NB * NS)                       // 32768
#define EMIT_ELEMS ((size_t)NB * NS * NH)    // 33554432

// ---------------- scratch (static __device__: no allocation) ----------------
__device__ float g_pre[(size_t)ROWS * 4 * NH];   // (t*64+b) x 4096  (x@Wx + bW, PERMUTED)
__device__ float g_fg [(size_t)ROWS * 2 * NH];   // (t*64+b) x 2048
__device__ float g_ft [(size_t)ROWS * NH];       // (t*64+b) x 1024
__device__ float g_hbuf0[NB * NH];
__device__ float g_hbuf1[NB * NH];
__device__ unsigned g_arrive_ctr;
__device__ unsigned g_release_ctr;

// ---------------- helpers ----------------
__device__ __forceinline__ uint32_t f2tf32(float x) {
    uint32_t r;
    asm("cvt.rna.tf32.f32 %0, %1;" : "=r"(r) : "f"(x));
    return r;
}
__device__ __forceinline__ float tf32f(float x) { return __uint_as_float(f2tf32(x)); }

__device__ __forceinline__ void mma_tf32(float d[4], const uint32_t a[4], const uint32_t b[2]) {
    asm volatile(
        "mma.sync.aligned.m16n8k8.row.col.f32.tf32.tf32.f32 "
        "{%0,%1,%2,%3}, {%4,%5,%6,%7}, {%8,%9}, {%0,%1,%2,%3};"
        : "+f"(d[0]), "+f"(d[1]), "+f"(d[2]), "+f"(d[3])
        : "r"(a[0]), "r"(a[1]), "r"(a[2]), "r"(a[3]), "r"(b[0]), "r"(b[1]));
}

__device__ __forceinline__ float sigf(float x) { return 1.0f / (1.0f + expf(-x)); }

// ---------------- init: zero h exchange buffer + reset barrier ----------------
__global__ void init_kernel() {
    int i = blockIdx.x * blockDim.x + threadIdx.x;
    if (i == 0) { g_arrive_ctr = 0u; g_release_ctr = 0u; }
    if (i < NB * NH) g_hbuf0[i] = 0.0f;
}

// ---------------- double-buffered tf32 GEMM: C = A(MxK)*B(KxN) + bias ----------------
// BM=128, BN=128, BK=32, 256 threads (8 warps 4x2), warp tile 32x64.
// Output row permutation (perm=1): row r=(b*512+t) stored at row (t*64+b).
#define BM 128
#define BN 128
#define BK 32
#define AS_STR 36      // 36 % 32 == 4 -> conflict-free A-fragment loads
#define BS_STR 136     // 136 % 32 == 8 -> conflict-free B-fragment loads
#define GEMM_SMEM ((2 * BM * AS_STR + 2 * BK * BS_STR) * 4)   // 71680 B

__device__ __forceinline__ void gemm_stage_store(
    float* As, float* Bs, int buf, const float4* ar, const float4* br, int tid)
{
    #pragma unroll
    for (int i = 0; i < 4; i++) {
        int idx = tid + i * 256;
        int r = idx >> 3, q = idx & 7;
        float4 v = ar[i];
        float4 cv = make_float4(tf32f(v.x), tf32f(v.y), tf32f(v.z), tf32f(v.w));
        *(float4*)&As[(size_t)buf * BM * AS_STR + r * AS_STR + q * 4] = cv;
    }
    #pragma unroll
    for (int i = 0; i < 4; i++) {
        int idx = tid + i * 256;
        int r = idx >> 5, q = idx & 31;
        float4 v = br[i];
        float4 cv = make_float4(tf32f(v.x), tf32f(v.y), tf32f(v.z), tf32f(v.w));
        *(float4*)&Bs[(size_t)buf * BK * BS_STR + r * BS_STR + q * 4] = cv;
    }
}

__global__ __launch_bounds__(256) void gemm_tf32_db(
    const float* __restrict__ A, const float* __restrict__ B,
    const float* __restrict__ bias, float* __restrict__ C,
    int K, int lda, int ldb, int ldc, int perm)
{
    extern __shared__ float sm[];
    float* As = sm;                         // 2 x 128 x 36
    float* Bs = sm + 2 * BM * AS_STR;       // 2 x 32 x 136

    const int tid  = threadIdx.x;
    const int warp = tid >> 5, lane = tid & 31;
    const int wm = warp >> 1, wn = warp & 1;
    const int gid = lane >> 2, kid = lane & 3;
    const int m0 = blockIdx.y * BM;
    const int n0 = blockIdx.x * BN;

    float acc[2][8][4];
    #pragma unroll
    for (int i = 0; i < 2; i++)
        #pragma unroll
        for (int j = 0; j < 8; j++)
            #pragma unroll
            for (int q = 0; q < 4; q++) acc[i][j][q] = 0.0f;

    float4 ar[4], br[4];
    // prologue: load kt=0 tile, stage to buf 0
    #pragma unroll
    for (int i = 0; i < 4; i++) {
        int idx = tid + i * 256;
        int r = idx >> 3, q = idx & 7;
        ar[i] = *(const float4*)(A + (size_t)(m0 + r) * lda + q * 4);
    }
    #pragma unroll
    for (int i = 0; i < 4; i++) {
        int idx = tid + i * 256;
        int r = idx >> 5, q = idx & 31;
        br[i] = *(const float4*)(B + (size_t)r * ldb + n0 + q * 4);
    }
    gemm_stage_store(As, Bs, 0, ar, br, tid);
    __syncthreads();

    for (int kt = 0; kt < K; kt += BK) {
        const int buf = (kt >> 5) & 1;
        const bool more = (kt + BK) < K;
        if (more) {
            #pragma unroll
            for (int i = 0; i < 4; i++) {
                int idx = tid + i * 256;
                int r = idx >> 3, q = idx & 7;
                ar[i] = *(const float4*)(A + (size_t)(m0 + r) * lda + kt + BK + q * 4);
            }
            #pragma unroll
            for (int i = 0; i < 4; i++) {
                int idx = tid + i * 256;
                int r = idx >> 5, q = idx & 31;
                br[i] = *(const float4*)(B + (size_t)(kt + BK + r) * ldb + n0 + q * 4);
            }
        }
        const float* Ac = As + (size_t)buf * BM * AS_STR;
        const float* Bc = Bs + (size_t)buf * BK * BS_STR;
        #pragma unroll
        for (int kk = 0; kk < BK; kk += 8) {
            uint32_t af[2][4], bf[8][2];
            #pragma unroll
            for (int mi = 0; mi < 2; mi++) {
                int r = wm * 32 + mi * 16 + gid;
                af[mi][0] = __float_as_uint(Ac[r * AS_STR + kk + kid]);
                af[mi][1] = __float_as_uint(Ac[(r + 8) * AS_STR + kk + kid]);
                af[mi][2] = __float_as_uint(Ac[r * AS_STR + kk + kid + 4]);
                af[mi][3] = __float_as_uint(Ac[(r + 8) * AS_STR + kk + kid + 4]);
            }
            #pragma unroll
            for (int ni = 0; ni < 8; ni++) {
                int cc = wn * 64 + ni * 8 + gid;
                bf[ni][0] = __float_as_uint(Bc[(kk + kid) * BS_STR + cc]);
                bf[ni][1] = __float_as_uint(Bc[(kk + kid + 4) * BS_STR + cc]);
            }
            #pragma unroll
            for (int mi = 0; mi < 2; mi++)
                #pragma unroll
                for (int ni = 0; ni < 8; ni++)
                    mma_tf32(acc[mi][ni], af[mi], bf[ni]);
        }
        if (more) gemm_stage_store(As, Bs, buf ^ 1, ar, br, tid);
        __syncthreads();
    }

    // Epilogue: bias + permuted store
    #pragma unroll
    for (int mi = 0; mi < 2; mi++) {
        int r = m0 + wm * 32 + mi * 16 + gid;
        int r0 = perm ? ((r & (NS - 1)) * NB + (r >> 9)) : r;
        int r1 = perm ? (((r + 8) & (NS - 1)) * NB + ((r + 8) >> 9)) : (r + 8);
        #pragma unroll
        for (int ni = 0; ni < 8; ni++) {
            int cc = n0 + wn * 64 + ni * 8 + 2 * kid;
            float b0 = bias[cc], b1 = bias[cc + 1];
            C[(size_t)r0 * ldc + cc]     = acc[mi][ni][0] + b0;
            C[(size_t)r0 * ldc + cc + 1] = acc[mi][ni][1] + b1;
            C[(size_t)r1 * ldc + cc]     = acc[mi][ni][2] + b0;
            C[(size_t)r1 * ldc + cc + 1] = acc[mi][ni][3] + b1;
        }
    }
}

// ---------------- field activation (vectorized): ft = sigmoid(r)*tanh(d) ----------------
__global__ void field_act_kernel() {
    size_t i = (size_t)blockIdx.x * blockDim.x + threadIdx.x;   // 0 .. EMIT/4-1
    size_t r = i >> 8;
    int j = (int)((i & 255) << 2);
    float4 rv = *(const float4*)(g_fg + r * 2048 + j);
    float4 dv = *(const float4*)(g_fg + r * 2048 + 1024 + j);
    float4 o;
    o.x = sigf(rv.x) * tanhf(dv.x);
    o.y = sigf(rv.y) * tanhf(dv.y);
    o.z = sigf(rv.z) * tanhf(dv.z);
    o.w = sigf(rv.w) * tanhf(dv.w);
    *(float4*)(g_ft + r * 1024 + j) = o;
}

// ---------------- persistent LSTM recurrence ----------------
// 128 blocks x 256 threads. Block owns 8 h-cols (32 gate cols); Wh slice lives
// in SMEM for all 512 steps; c/h cell state lives in registers; h exchanged
// via global double buffer with a custom grid barrier per step.
#define PBLK 128
#define WH_STR 40      // 40 % 32 == 8 -> conflict-free B-fragment loads
#define P_AS_STR 36
#define PERS_SMEM ((1024 * WH_STR + 2 * 64 * P_AS_STR + 64 * P_AS_STR) * 4)  // 191488 B

__device__ __forceinline__ void grid_sync_step(int t) {
    __threadfence();
    __syncthreads();
    if (threadIdx.x == 0) {
        unsigned prev;
        asm volatile("atom.add.release.gpu.u32 %0, [%1], %2;"
                     : "=r"(prev) : "l"(&g_arrive_ctr), "r"(1u) : "memory");
        if (prev + 1u == (unsigned)(PBLK * (t + 1))) {
            asm volatile("st.release.gpu.u32 [%0], %1;"
                         :: "l"(&g_release_ctr), "r"((unsigned)(t + 1)) : "memory");
        }
        unsigned r;
        do {
            asm volatile("ld.acquire.gpu.u32 %0, [%1];" : "=r"(r) : "l"(&g_release_ctr) : "memory");
        } while (r < (unsigned)(t + 1));
    }
    __syncthreads();
}

__global__ __launch_bounds__(256) void lstm_persistent(
    const float* __restrict__ W, const int* __restrict__ len, float* __restrict__ out)
{
    extern __shared__ float sm[];
    float* Whs = sm;                                 // 1024 x 40 (tf32-converted)
    float* Asb = sm + 1024 * WH_STR;                 // 2 x 64 x 36
    float* Gs  = Asb + 2 * 64 * P_AS_STR;            // 64 x 36
    __shared__ int lens[NB];

    const int tid  = threadIdx.x;
    const int warp = tid >> 5, lane = tid & 31;
    const int wm = warp >> 1, wg = warp & 1;
    const int gid = lane >> 2, kid = lane & 3;
    const int hbase = blockIdx.x * 8;
    const float* Wh = W + (size_t)1024 * 4096;

    // Load this block's Wh slice into SMEM, pre-converted to tf32.
    for (int i = tid; i < 1024 * 32; i += 256) {
        int k = i >> 5, c = i & 31;
        int g = c >> 3, hc = c & 7;
        Whs[k * WH_STR + c] = tf32f(Wh[(size_t)k * 4096 + g * 1024 + hbase + hc]);
    }
    if (tid < NB) lens[tid] = len[tid];
    __syncthreads();

    // Epilogue cell mapping: thread -> (batch eb, hcol pair ehc, ehc+1)
    const int eb  = tid >> 2;
    const int ehc = (tid & 3) * 2;
    const int mylen = lens[eb];
    const int hcol  = hbase + ehc;
    float2 creg = make_float2(0.f, 0.f);
    float2 hreg = make_float2(0.f, 0.f);

    // h-chunk load indices (each thread: 2 float4)
    const int r0 = tid >> 3,        q0 = tid & 7;
    const int r1 = (tid + 256) >> 3;

    for (int t = 0; t < NS; t++) {
        const float* hr = (t & 1) ? g_hbuf1 : g_hbuf0;
        float*       hw = (t & 1) ? g_hbuf0 : g_hbuf1;

        // Prefetch epilogue operands (DRAM) — land during GEMM
        size_t prow = (size_t)t * NB + eb;
        float2 pg0 = *(const float2*)(g_pre + prow * 4096 +          hcol);
        float2 pg1 = *(const float2*)(g_pre + prow * 4096 + 1024 +   hcol);
        float2 pg2 = *(const float2*)(g_pre + prow * 4096 + 2048 +   hcol);
        float2 pg3 = *(const float2*)(g_pre + prow * 4096 + 3072 +   hcol);
        float2 ftv = *(const float2*)(g_ft  + prow * 1024 +          hcol);

        float acc[2][4] = {{0.f,0.f,0.f,0.f},{0.f,0.f,0.f,0.f}};

        // chunk 0 stage
        float4 p0 = *(const float4*)(hr + (size_t)r0 * NH + q0 * 4);
        float4 p1 = *(const float4*)(hr + (size_t)r1 * NH + q0 * 4);
        {
            float4 c0 = make_float4(tf32f(p0.x), tf32f(p0.y), tf32f(p0.z), tf32f(p0.w));
            float4 c1 = make_float4(tf32f(p1.x), tf32f(p1.y), tf32f(p1.z), tf32f(p1.w));
            *(float4*)&Asb[r0 * P_AS_STR + q0 * 4] = c0;
            *(float4*)&Asb[r1 * P_AS_STR + q0 * 4] = c1;
        }
        __syncthreads();

        for (int ci = 0; ci < 32; ci++) {
            if (ci < 31) {
                int kn = (ci + 1) * 32;
                p0 = *(const float4*)(hr + (size_t)r0 * NH + kn + q0 * 4);
                p1 = *(const float4*)(hr + (size_t)r1 * NH + kn + q0 * 4);
            }
            const float* cur = Asb + (size_t)(ci & 1) * 64 * P_AS_STR;
            const int ktg = ci * 32;
            #pragma unroll
            for (int kk = 0; kk < 32; kk += 8) {
                uint32_t af[4], bf[2][2];
                int rr = wm * 16 + gid;
                af[0] = __float_as_uint(cur[rr * P_AS_STR + kk + kid]);
                af[1] = __float_as_uint(cur[(rr + 8) * P_AS_STR + kk + kid]);
                af[2] = __float_as_uint(cur[rr * P_AS_STR + kk + kid + 4]);
                af[3] = __float_as_uint(cur[(rr + 8) * P_AS_STR + kk + kid + 4]);
                int kg = ktg + kk;
                #pragma unroll
                for (int ni = 0; ni < 2; ni++) {
                    int cc = wg * 16 + ni * 8 + gid;
                    bf[ni][0] = __float_as_uint(Whs[(kg + kid) * WH_STR + cc]);
                    bf[ni][1] = __float_as_uint(Whs[(kg + kid + 4) * WH_STR + cc]);
                    mma_tf32(acc[ni], af, bf[ni]);
                }
            }
            if (ci < 31) {
                int nb = (ci + 1) & 1;
                float4 c0 = make_float4(tf32f(p0.x), tf32f(p0.y), tf32f(p0.z), tf32f(p0.w));
                float4 c1 = make_float4(tf32f(p1.x), tf32f(p1.y), tf32f(p1.z), tf32f(p1.w));
                *(float4*)&Asb[(size_t)nb * 64 * P_AS_STR + r0 * P_AS_STR + q0 * 4] = c0;
                *(float4*)&Asb[(size_t)nb * 64 * P_AS_STR + r1 * P_AS_STR + q0 * 4] = c1;
            }
            __syncthreads();
        }

        // Gate exchange: acc -> Gs[batch][gatecol]
        {
            int rr = wm * 16 + gid;
            #pragma unroll
            for (int ni = 0; ni < 2; ni++) {
                int cc = wg * 16 + ni * 8 + 2 * kid;
                Gs[rr * P_AS_STR + cc]           = acc[ni][0];
                Gs[rr * P_AS_STR + cc + 1]       = acc[ni][1];
                Gs[(rr + 8) * P_AS_STR + cc]     = acc[ni][2];
                Gs[(rr + 8) * P_AS_STR + cc + 1] = acc[ni][3];
            }
        }
        __syncthreads();

        // Cell update (2 cells per thread)
        {
            bool act = (t < mylen);
            float gi0 = Gs[eb * P_AS_STR + ehc]      + pg0.x;
            float gj0 = Gs[eb * P_AS_STR + 8 + ehc]  + pg1.x;
            float gf0 = Gs[eb * P_AS_STR + 16 + ehc] + pg2.x;
            float go0 = Gs[eb * P_AS_STR + 24 + ehc] + pg3.x;
            float gi1 = Gs[eb * P_AS_STR + ehc + 1]      + pg0.y;
            float gj1 = Gs[eb * P_AS_STR + 8 + ehc + 1]  + pg1.y;
            float gf1 = Gs[eb * P_AS_STR + 16 + ehc + 1] + pg2.y;
            float go1 = Gs[eb * P_AS_STR + 24 + ehc + 1] + pg3.y;

            float cn0 = sigf(gf0 + 1.0f) * creg.x + sigf(gi0) * tanhf(gj0) + ftv.x;
            float hn0 = sigf(go0) * tanhf(cn0);
            float cn1 = sigf(gf1 + 1.0f) * creg.y + sigf(gi1) * tanhf(gj1) + ftv.y;
            float hn1 = sigf(go1) * tanhf(cn1);

            float2 emit = make_float2(act ? hn0 : 0.0f, act ? hn1 : 0.0f);
            creg.x = act ? cn0 : creg.x;  creg.y = act ? cn1 : creg.y;
            hreg.x = act ? hn0 : hreg.x;  hreg.y = act ? hn1 : hreg.y;

            *(float2*)(out + ((size_t)eb * NS + t) * NH + hcol) = emit;
            *(float2*)(hw + (size_t)eb * NH + hcol) = hreg;
        }

        if (t < NS - 1) grid_sync_step(t);
    }

    // Finals
    *(float2*)(out + EMIT_ELEMS + (size_t)eb * NH + hcol)           = hreg;
    *(float2*)(out + EMIT_ELEMS + NB * NH + (size_t)eb * NH + hcol) = creg;
}

// ---------------- host ----------------
extern "C" void kernel_launch(void* const* d_in, const int* in_sizes, int n_in,
                              void* d_out, int out_size)
{
    const float* X   = (const float*)d_in[0];  // (64, 512, 1024)
    const float* F   = (const float*)d_in[1];  // (64, 512, 256)
    const int*   len = (const int*)  d_in[2];  // (64,)
    const float* W   = (const float*)d_in[3];  // (2048, 4096)
    const float* bW  = (const float*)d_in[4];  // (4096,)
    const float* W1  = (const float*)d_in[5];  // (256, 2048)
    const float* bW1 = (const float*)d_in[6];  // (2048,)
    float* out = (float*)d_out;

    float *pre_p, *fg_p;
    cudaGetSymbolAddress((void**)&pre_p, g_pre);
    cudaGetSymbolAddress((void**)&fg_p,  g_fg);

    static bool attrs_set = false;
    if (!attrs_set) {
        cudaFuncSetAttribute(gemm_tf32_db,
                             cudaFuncAttributeMaxDynamicSharedMemorySize, GEMM_SMEM);
        cudaFuncSetAttribute(lstm_persistent,
                             cudaFuncAttributeMaxDynamicSharedMemorySize, PERS_SMEM);
        attrs_set = true;
    }

    // reset barrier + zero h buffer
    init_kernel<<<256, 256>>>();

    // pre = X @ W[0:1024,:] + bW  -> permuted rows (t*64+b)
    gemm_tf32_db<<<dim3(4 * NH / BN, ROWS / BM), 256, GEMM_SMEM>>>(
        X, W, bW, pre_p, NUNI, NUNI, 4 * NH, 4 * NH, 1);

    // fg = F @ W1 + bW1 -> permuted rows
    gemm_tf32_db<<<dim3(2 * NH / BN, ROWS / BM), 256, GEMM_SMEM>>>(
        F, W1, bW1, fg_p, NFLD, NFLD, 2 * NH, 2 * NH, 1);

    // field term
    field_act_kernel<<<(int)(EMIT_ELEMS / 4 / 256), 256>>>();

    // recurrence: one persistent kernel
    lstm_persistent<<<PBLK, 256, PERS_SMEM>>>(W, len, out);
}

// round 4
// speedup vs baseline: 1.6630x; 1.2893x over previous
#include <cuda_runtime.h>
#include <cstdint>
#include <cstddef>

// Problem constants
#define NB   64
#define NS   512
#define NUNI 1024
#define NH   1024
#define NFLD 256
#define ROWS (NB * NS)                       // 32768
#define EMIT_ELEMS ((size_t)NB * NS * NH)    // 33554432

// ---------------- scratch (static __device__: no allocation) ----------------
__device__ float g_pre[(size_t)ROWS * 4 * NH];   // (t*64+b) x 4096  (x@Wx + bW, PERMUTED)
__device__ float g_ft [(size_t)ROWS * NH];       // (t*64+b) x 1024
__device__ float g_hbuf0[NB * NH];
__device__ float g_hbuf1[NB * NH];
__device__ unsigned g_arrive_ctr;

// ---------------- helpers ----------------
__device__ __forceinline__ uint32_t f2tf32(float x) {
    uint32_t r;
    asm("cvt.rna.tf32.f32 %0, %1;" : "=r"(r) : "f"(x));
    return r;
}
__device__ __forceinline__ float tf32f(float x) { return __uint_as_float(f2tf32(x)); }

__device__ __forceinline__ void mma_tf32(float d[4], const uint32_t a[4], const uint32_t b[2]) {
    asm volatile(
        "mma.sync.aligned.m16n8k8.row.col.f32.tf32.tf32.f32 "
        "{%0,%1,%2,%3}, {%4,%5,%6,%7}, {%8,%9}, {%0,%1,%2,%3};"
        : "+f"(d[0]), "+f"(d[1]), "+f"(d[2]), "+f"(d[3])
        : "r"(a[0]), "r"(a[1]), "r"(a[2]), "r"(a[3]), "r"(b[0]), "r"(b[1]));
}

__device__ __forceinline__ float sigf(float x) { return 1.0f / (1.0f + expf(-x)); }

// ---------------- init: zero h exchange buffer + reset barrier ----------------
__global__ void init_kernel() {
    int i = blockIdx.x * blockDim.x + threadIdx.x;
    if (i == 0) g_arrive_ctr = 0u;
    if (i < NB * NH) g_hbuf0[i] = 0.0f;
}

// ---------------- double-buffered tf32 GEMM: C = A(MxK)*B(KxN) + bias ----------------
// BM=128, BN=128, BK=32, 256 threads (8 warps 4x2), warp tile 32x64.
// Output row permutation: row r=(b*512+t) stored at row (t*64+b).
#define BM 128
#define BN 128
#define BK 32
#define AS_STR 36
#define BS_STR 136
#define GEMM_SMEM ((2 * BM * AS_STR + 2 * BK * BS_STR) * 4)   // 71680 B

__device__ __forceinline__ void gemm_stage_store(
    float* As, float* Bs, int buf, const float4* ar, const float4* br, int tid)
{
    #pragma unroll
    for (int i = 0; i < 4; i++) {
        int idx = tid + i * 256;
        int r = idx >> 3, q = idx & 7;
        float4 v = ar[i];
        float4 cv = make_float4(tf32f(v.x), tf32f(v.y), tf32f(v.z), tf32f(v.w));
        *(float4*)&As[(size_t)buf * BM * AS_STR + r * AS_STR + q * 4] = cv;
    }
    #pragma unroll
    for (int i = 0; i < 4; i++) {
        int idx = tid + i * 256;
        int r = idx >> 5, q = idx & 31;
        float4 v = br[i];
        float4 cv = make_float4(tf32f(v.x), tf32f(v.y), tf32f(v.z), tf32f(v.w));
        *(float4*)&Bs[(size_t)buf * BK * BS_STR + r * BS_STR + q * 4] = cv;
    }
}

__global__ __launch_bounds__(256) void gemm_tf32_db(
    const float* __restrict__ A, const float* __restrict__ B,
    const float* __restrict__ bias, float* __restrict__ C,
    int K, int lda, int ldb, int ldc)
{
    extern __shared__ float sm[];
    float* As = sm;
    float* Bs = sm + 2 * BM * AS_STR;

    const int tid  = threadIdx.x;
    const int warp = tid >> 5, lane = tid & 31;
    const int wm = warp >> 1, wn = warp & 1;
    const int gid = lane >> 2, kid = lane & 3;
    const int m0 = blockIdx.y * BM;
    const int n0 = blockIdx.x * BN;

    float acc[2][8][4];
    #pragma unroll
    for (int i = 0; i < 2; i++)
        #pragma unroll
        for (int j = 0; j < 8; j++)
            #pragma unroll
            for (int q = 0; q < 4; q++) acc[i][j][q] = 0.0f;

    float4 ar[4], br[4];
    #pragma unroll
    for (int i = 0; i < 4; i++) {
        int idx = tid + i * 256;
        int r = idx >> 3, q = idx & 7;
        ar[i] = *(const float4*)(A + (size_t)(m0 + r) * lda + q * 4);
    }
    #pragma unroll
    for (int i = 0; i < 4; i++) {
        int idx = tid + i * 256;
        int r = idx >> 5, q = idx & 31;
        br[i] = *(const float4*)(B + (size_t)r * ldb + n0 + q * 4);
    }
    gemm_stage_store(As, Bs, 0, ar, br, tid);
    __syncthreads();

    for (int kt = 0; kt < K; kt += BK) {
        const int buf = (kt >> 5) & 1;
        const bool more = (kt + BK) < K;
        if (more) {
            #pragma unroll
            for (int i = 0; i < 4; i++) {
                int idx = tid + i * 256;
                int r = idx >> 3, q = idx & 7;
                ar[i] = *(const float4*)(A + (size_t)(m0 + r) * lda + kt + BK + q * 4);
            }
            #pragma unroll
            for (int i = 0; i < 4; i++) {
                int idx = tid + i * 256;
                int r = idx >> 5, q = idx & 31;
                br[i] = *(const float4*)(B + (size_t)(kt + BK + r) * ldb + n0 + q * 4);
            }
        }
        const float* Ac = As + (size_t)buf * BM * AS_STR;
        const float* Bc = Bs + (size_t)buf * BK * BS_STR;
        #pragma unroll
        for (int kk = 0; kk < BK; kk += 8) {
            uint32_t af[2][4], bf[8][2];
            #pragma unroll
            for (int mi = 0; mi < 2; mi++) {
                int r = wm * 32 + mi * 16 + gid;
                af[mi][0] = __float_as_uint(Ac[r * AS_STR + kk + kid]);
                af[mi][1] = __float_as_uint(Ac[(r + 8) * AS_STR + kk + kid]);
                af[mi][2] = __float_as_uint(Ac[r * AS_STR + kk + kid + 4]);
                af[mi][3] = __float_as_uint(Ac[(r + 8) * AS_STR + kk + kid + 4]);
            }
            #pragma unroll
            for (int ni = 0; ni < 8; ni++) {
                int cc = wn * 64 + ni * 8 + gid;
                bf[ni][0] = __float_as_uint(Bc[(kk + kid) * BS_STR + cc]);
                bf[ni][1] = __float_as_uint(Bc[(kk + kid + 4) * BS_STR + cc]);
            }
            #pragma unroll
            for (int mi = 0; mi < 2; mi++)
                #pragma unroll
                for (int ni = 0; ni < 8; ni++)
                    mma_tf32(acc[mi][ni], af[mi], bf[ni]);
        }
        if (more) gemm_stage_store(As, Bs, buf ^ 1, ar, br, tid);
        __syncthreads();
    }

    // Epilogue: bias + permuted store  (row b*512+t -> t*64+b)
    #pragma unroll
    for (int mi = 0; mi < 2; mi++) {
        int r = m0 + wm * 32 + mi * 16 + gid;
        int r0 = (r & (NS - 1)) * NB + (r >> 9);
        int r1 = ((r + 8) & (NS - 1)) * NB + ((r + 8) >> 9);
        #pragma unroll
        for (int ni = 0; ni < 8; ni++) {
            int cc = n0 + wn * 64 + ni * 8 + 2 * kid;
            float b0 = bias[cc], b1 = bias[cc + 1];
            C[(size_t)r0 * ldc + cc]     = acc[mi][ni][0] + b0;
            C[(size_t)r0 * ldc + cc + 1] = acc[mi][ni][1] + b1;
            C[(size_t)r1 * ldc + cc]     = acc[mi][ni][2] + b0;
            C[(size_t)r1 * ldc + cc + 1] = acc[mi][ni][3] + b1;
        }
    }
}

// ---------------- fused field GEMM: ft = sigmoid(F@W1r + br) * tanh(F@W1d + bd) ----------
// Block computes a 64-col r-strip (cols n0..n0+63 of W1) and the matching
// d-strip (cols 1024+n0..). wn=0 warps own r, wn=1 warps own d. d exchanged
// through smem in the epilogue; ft written directly (permuted rows).
__global__ __launch_bounds__(256) void gemm_field_fused(
    const float* __restrict__ A, const float* __restrict__ B,
    const float* __restrict__ bias, float* __restrict__ C)
{
    extern __shared__ float sm[];
    float* As = sm;
    float* Bs = sm + 2 * BM * AS_STR;
    float* Ds = sm;                        // reuse As region in epilogue (128x68 < 2*128*36)

    const int tid  = threadIdx.x;
    const int warp = tid >> 5, lane = tid & 31;
    const int wm = warp >> 1, wn = warp & 1;
    const int gid = lane >> 2, kid = lane & 3;
    const int m0 = blockIdx.y * BM;
    const int n0 = blockIdx.x * 64;        // r-strip base (d-strip at 1024+n0)
    const int K = NFLD, lda = NFLD, ldb = 2 * NH;

    float acc[2][8][4];
    #pragma unroll
    for (int i = 0; i < 2; i++)
        #pragma unroll
        for (int j = 0; j < 8; j++)
            #pragma unroll
            for (int q = 0; q < 4; q++) acc[i][j][q] = 0.0f;

    float4 ar[4], br[4];
    #pragma unroll
    for (int i = 0; i < 4; i++) {
        int idx = tid + i * 256;
        int r = idx >> 3, q = idx & 7;
        ar[i] = *(const float4*)(A + (size_t)(m0 + r) * lda + q * 4);
    }
    #pragma unroll
    for (int i = 0; i < 4; i++) {
        int idx = tid + i * 256;
        int r = idx >> 5, q = idx & 31;
        int col = (q < 16) ? (n0 + q * 4) : (NH + n0 + (q - 16) * 4);
        br[i] = *(const float4*)(B + (size_t)r * ldb + col);
    }
    gemm_stage_store(As, Bs, 0, ar, br, tid);
    __syncthreads();

    for (int kt = 0; kt < K; kt += BK) {
        const int buf = (kt >> 5) & 1;
        const bool more = (kt + BK) < K;
        if (more) {
            #pragma unroll
            for (int i = 0; i < 4; i++) {
                int idx = tid + i * 256;
                int r = idx >> 3, q = idx & 7;
                ar[i] = *(const float4*)(A + (size_t)(m0 + r) * lda + kt + BK + q * 4);
            }
            #pragma unroll
            for (int i = 0; i < 4; i++) {
                int idx = tid + i * 256;
                int r = idx >> 5, q = idx & 31;
                int col = (q < 16) ? (n0 + q * 4) : (NH + n0 + (q - 16) * 4);
                br[i] = *(const float4*)(B + (size_t)(kt + BK + r) * ldb + col);
            }
        }
        const float* Ac = As + (size_t)buf * BM * AS_STR;
        const float* Bc = Bs + (size_t)buf * BK * BS_STR;
        #pragma unroll
        for (int kk = 0; kk < BK; kk += 8) {
            uint32_t af[2][4], bf[8][2];
            #pragma unroll
            for (int mi = 0; mi < 2; mi++) {
                int r = wm * 32 + mi * 16 + gid;
                af[mi][0] = __float_as_uint(Ac[r * AS_STR + kk + kid]);
                af[mi][1] = __float_as_uint(Ac[(r + 8) * AS_STR + kk + kid]);
                af[mi][2] = __float_as_uint(Ac[r * AS_STR + kk + kid + 4]);
                af[mi][3] = __float_as_uint(Ac[(r + 8) * AS_STR + kk + kid + 4]);
            }
            #pragma unroll
            for (int ni = 0; ni < 8; ni++) {
                int cc = wn * 64 + ni * 8 + gid;
                bf[ni][0] = __float_as_uint(Bc[(kk + kid) * BS_STR + cc]);
                bf[ni][1] = __float_as_uint(Bc[(kk + kid + 4) * BS_STR + cc]);
            }
            #pragma unroll
            for (int mi = 0; mi < 2; mi++)
                #pragma unroll
                for (int ni = 0; ni < 8; ni++)
                    mma_tf32(acc[mi][ni], af[mi], bf[ni]);
        }
        __syncthreads();
        if (more) { gemm_stage_store(As, Bs, buf ^ 1, ar, br, tid); __syncthreads(); }
    }

    // Epilogue: wn=1 (d) warps publish d+bias to smem; wn=0 warps write ft.
    if (wn == 1) {
        #pragma unroll
        for (int mi = 0; mi < 2; mi++) {
            int lr = wm * 32 + mi * 16 + gid;
            #pragma unroll
            for (int ni = 0; ni < 8; ni++) {
                int cc = ni * 8 + 2 * kid;        // 0..63 within d strip
                float b0 = bias[NH + n0 + cc], b1 = bias[NH + n0 + cc + 1];
                Ds[lr * 68 + cc]           = acc[mi][ni][0] + b0;
                Ds[lr * 68 + cc + 1]       = acc[mi][ni][1] + b1;
                Ds[(lr + 8) * 68 + cc]     = acc[mi][ni][2] + b0;
                Ds[(lr + 8) * 68 + cc + 1] = acc[mi][ni][3] + b1;
            }
        }
    }
    __syncthreads();
    if (wn == 0) {
        #pragma unroll
        for (int mi = 0; mi < 2; mi++) {
            int lr = wm * 32 + mi * 16 + gid;
            int r = m0 + lr;
            int r0 = (r & (NS - 1)) * NB + (r >> 9);
            int r1 = ((r + 8) & (NS - 1)) * NB + ((r + 8) >> 9);
            #pragma unroll
            for (int ni = 0; ni < 8; ni++) {
                int cc = ni * 8 + 2 * kid;
                float b0 = bias[n0 + cc], b1 = bias[n0 + cc + 1];
                float2 o0, o1;
                o0.x = sigf(acc[mi][ni][0] + b0) * tanhf(Ds[lr * 68 + cc]);
                o0.y = sigf(acc[mi][ni][1] + b1) * tanhf(Ds[lr * 68 + cc + 1]);
                o1.x = sigf(acc[mi][ni][2] + b0) * tanhf(Ds[(lr + 8) * 68 + cc]);
                o1.y = sigf(acc[mi][ni][3] + b1) * tanhf(Ds[(lr + 8) * 68 + cc + 1]);
                *(float2*)(C + (size_t)r0 * NH + n0 + cc) = o0;
                *(float2*)(C + (size_t)r1 * NH + n0 + cc) = o1;
            }
        }
    }
}

// ---------------- persistent LSTM recurrence ----------------
// 128 blocks x 256 threads. Block owns 8 h-cols (32 gate cols); Wh slice lives
// in SMEM for all 512 steps; c/h cell state in registers; h exchanged via
// global double buffer (L1-bypassed) with a spin-on-arrive grid barrier.
#define PBLK 128
#define WH_STR 40
#define KC 64
#define P_AS_STR 68
#define PERS_SMEM ((1024 * WH_STR + 2 * 64 * P_AS_STR) * 4)   // 198656 B

__global__ __launch_bounds__(256) void lstm_persistent(
    const float* __restrict__ W, const int* __restrict__ len, float* __restrict__ out)
{
    extern __shared__ float sm[];
    float* Whs = sm;                                 // 1024 x 40 (tf32-converted)
    float* Asb = sm + 1024 * WH_STR;                 // 2 x 64 x 68
    float* Gs  = Asb;                                // alias buffer 0 (epilogue only)
    __shared__ int lens[NB];

    const int tid  = threadIdx.x;
    const int warp = tid >> 5, lane = tid & 31;
    const int wm = warp >> 1, wg = warp & 1;
    const int gid = lane >> 2, kid = lane & 3;
    const int hbase = blockIdx.x * 8;
    const float* Wh = W + (size_t)1024 * 4096;

    for (int i = tid; i < 1024 * 32; i += 256) {
        int k = i >> 5, c = i & 31;
        int g = c >> 3, hc = c & 7;
        Whs[k * WH_STR + c] = tf32f(Wh[(size_t)k * 4096 + g * 1024 + hbase + hc]);
    }
    if (tid < NB) lens[tid] = len[tid];
    __syncthreads();

    const int eb  = tid >> 2;
    const int ehc = (tid & 3) * 2;
    const int mylen = lens[eb];
    const int hcol  = hbase + ehc;
    float2 creg = make_float2(0.f, 0.f);
    float2 hreg = make_float2(0.f, 0.f);

    // chunk staging: 64 rows x 16 float4; 4 float4 per thread
    const int srow[4] = { tid >> 4, (tid + 256) >> 4, (tid + 512) >> 4, (tid + 768) >> 4 };
    const int sq = tid & 15;

    // Prefetch epilogue operands for t=0
    float2 pg0, pg1, pg2, pg3, ftv;
    {
        size_t prow = (size_t)0 * NB + eb;
        pg0 = *(const float2*)(g_pre + prow * 4096 +        hcol);
        pg1 = *(const float2*)(g_pre + prow * 4096 + 1024 + hcol);
        pg2 = *(const float2*)(g_pre + prow * 4096 + 2048 + hcol);
        pg3 = *(const float2*)(g_pre + prow * 4096 + 3072 + hcol);
        ftv = *(const float2*)(g_ft  + prow * 1024 +        hcol);
    }

    for (int t = 0; t < NS; t++) {
        const float* hr = (t & 1) ? g_hbuf1 : g_hbuf0;
        float*       hw = (t & 1) ? g_hbuf0 : g_hbuf1;

        float acc[2][4] = {{0.f,0.f,0.f,0.f},{0.f,0.f,0.f,0.f}};

        // stage chunk 0 (L1-bypass loads: other SMs wrote h last step)
        float4 p[4];
        #pragma unroll
        for (int j = 0; j < 4; j++)
            p[j] = __ldcg((const float4*)(hr + (size_t)srow[j] * NH + sq * 4));
        #pragma unroll
        for (int j = 0; j < 4; j++)
            *(float4*)&Asb[srow[j] * P_AS_STR + sq * 4] =
                make_float4(tf32f(p[j].x), tf32f(p[j].y), tf32f(p[j].z), tf32f(p[j].w));
        __syncthreads();

        for (int ci = 0; ci < 16; ci++) {
            if (ci < 15) {
                int kn = (ci + 1) * KC;
                #pragma unroll
                for (int j = 0; j < 4; j++)
                    p[j] = __ldcg((const float4*)(hr + (size_t)srow[j] * NH + kn + sq * 4));
            }
            const float* cur = Asb + (size_t)(ci & 1) * 64 * P_AS_STR;
            const int ktg = ci * KC;
            #pragma unroll
            for (int kk = 0; kk < KC; kk += 8) {
                uint32_t af[4], bf[2][2];
                int rr = wm * 16 + gid;
                af[0] = __float_as_uint(cur[rr * P_AS_STR + kk + kid]);
                af[1] = __float_as_uint(cur[(rr + 8) * P_AS_STR + kk + kid]);
                af[2] = __float_as_uint(cur[rr * P_AS_STR + kk + kid + 4]);
                af[3] = __float_as_uint(cur[(rr + 8) * P_AS_STR + kk + kid + 4]);
                int kg = ktg + kk;
                #pragma unroll
                for (int ni = 0; ni < 2; ni++) {
                    int cc = wg * 16 + ni * 8 + gid;
                    bf[ni][0] = __float_as_uint(Whs[(kg + kid) * WH_STR + cc]);
                    bf[ni][1] = __float_as_uint(Whs[(kg + kid + 4) * WH_STR + cc]);
                    mma_tf32(acc[ni], af, bf[ni]);
                }
            }
            if (ci < 15) {
                int nb = (ci + 1) & 1;
                #pragma unroll
                for (int j = 0; j < 4; j++)
                    *(float4*)&Asb[(size_t)nb * 64 * P_AS_STR + srow[j] * P_AS_STR + sq * 4] =
                        make_float4(tf32f(p[j].x), tf32f(p[j].y), tf32f(p[j].z), tf32f(p[j].w));
            }
            __syncthreads();
        }

        // Gate exchange (Gs aliases A buffer 0 — free after final sync)
        {
            int rr = wm * 16 + gid;
            #pragma unroll
            for (int ni = 0; ni < 2; ni++) {
                int cc = wg * 16 + ni * 8 + 2 * kid;
                Gs[rr * P_AS_STR + cc]           = acc[ni][0];
                Gs[rr * P_AS_STR + cc + 1]       = acc[ni][1];
                Gs[(rr + 8) * P_AS_STR + cc]     = acc[ni][2];
                Gs[(rr + 8) * P_AS_STR + cc + 1] = acc[ni][3];
            }
        }
        __syncthreads();

        // Cell update (2 cells per thread)
        bool act = (t < mylen);
        float gi0 = Gs[eb * P_AS_STR + ehc]      + pg0.x;
        float gj0 = Gs[eb * P_AS_STR + 8 + ehc]  + pg1.x;
        float gf0 = Gs[eb * P_AS_STR + 16 + ehc] + pg2.x;
        float go0 = Gs[eb * P_AS_STR + 24 + ehc] + pg3.x;
        float gi1 = Gs[eb * P_AS_STR + ehc + 1]      + pg0.y;
        float gj1 = Gs[eb * P_AS_STR + 8 + ehc + 1]  + pg1.y;
        float gf1 = Gs[eb * P_AS_STR + 16 + ehc + 1] + pg2.y;
        float go1 = Gs[eb * P_AS_STR + 24 + ehc + 1] + pg3.y;

        float cn0 = sigf(gf0 + 1.0f) * creg.x + sigf(gi0) * tanhf(gj0) + ftv.x;
        float hn0 = sigf(go0) * tanhf(cn0);
        float cn1 = sigf(gf1 + 1.0f) * creg.y + sigf(gi1) * tanhf(gj1) + ftv.y;
        float hn1 = sigf(go1) * tanhf(cn1);

        float2 emit = make_float2(act ? hn0 : 0.0f, act ? hn1 : 0.0f);
        creg.x = act ? cn0 : creg.x;  creg.y = act ? cn1 : creg.y;
        hreg.x = act ? hn0 : hreg.x;  hreg.y = act ? hn1 : hreg.y;

        // h must be globally visible before the barrier arrive
        *(float2*)(hw + (size_t)eb * NH + hcol) = hreg;
        __threadfence();
        __syncthreads();

        if (t < NS - 1) {
            if (tid == 0) {
                unsigned prev;
                asm volatile("atom.add.release.gpu.u32 %0, [%1], %2;"
                             : "=r"(prev) : "l"(&g_arrive_ctr), "r"(1u) : "memory");
            }
            // off critical path: emit store + next-step operand prefetch
            *(float2*)(out + ((size_t)eb * NS + t) * NH + hcol) = emit;
            {
                size_t prow = (size_t)(t + 1) * NB + eb;
                pg0 = *(const float2*)(g_pre + prow * 4096 +        hcol);
                pg1 = *(const float2*)(g_pre + prow * 4096 + 1024 + hcol);
                pg2 = *(const float2*)(g_pre + prow * 4096 + 2048 + hcol);
                pg3 = *(const float2*)(g_pre + prow * 4096 + 3072 + hcol);
                ftv = *(const float2*)(g_ft  + prow * 1024 +        hcol);
            }
            if (tid == 0) {
                unsigned target = (unsigned)(PBLK * (t + 1)), v;
                do {
                    asm volatile("ld.acquire.gpu.u32 %0, [%1];"
                                 : "=r"(v) : "l"(&g_arrive_ctr) : "memory");
                } while (v < target);
            }
            __syncthreads();
        } else {
            *(float2*)(out + ((size_t)eb * NS + t) * NH + hcol) = emit;
        }
    }

    // Finals
    *(float2*)(out + EMIT_ELEMS + (size_t)eb * NH + hcol)           = hreg;
    *(float2*)(out + EMIT_ELEMS + NB * NH + (size_t)eb * NH + hcol) = creg;
}

// ---------------- host ----------------
extern "C" void kernel_launch(void* const* d_in, const int* in_sizes, int n_in,
                              void* d_out, int out_size)
{
    const float* X   = (const float*)d_in[0];  // (64, 512, 1024)
    const float* F   = (const float*)d_in[1];  // (64, 512, 256)
    const int*   len = (const int*)  d_in[2];  // (64,)
    const float* W   = (const float*)d_in[3];  // (2048, 4096)
    const float* bW  = (const float*)d_in[4];  // (4096,)
    const float* W1  = (const float*)d_in[5];  // (256, 2048)
    const float* bW1 = (const float*)d_in[6];  // (2048,)
    float* out = (float*)d_out;

    float *pre_p, *ft_p;
    cudaGetSymbolAddress((void**)&pre_p, g_pre);
    cudaGetSymbolAddress((void**)&ft_p,  g_ft);

    static bool attrs_set = false;
    if (!attrs_set) {
        cudaFuncSetAttribute(gemm_tf32_db,
                             cudaFuncAttributeMaxDynamicSharedMemorySize, GEMM_SMEM);
        cudaFuncSetAttribute(gemm_field_fused,
                             cudaFuncAttributeMaxDynamicSharedMemorySize, GEMM_SMEM);
        cudaFuncSetAttribute(lstm_persistent,
                             cudaFuncAttributeMaxDynamicSharedMemorySize, PERS_SMEM);
        attrs_set = true;
    }

    // reset barrier + zero h buffer
    init_kernel<<<256, 256>>>();

    // pre = X @ W[0:1024,:] + bW  -> permuted rows (t*64+b)
    gemm_tf32_db<<<dim3(4 * NH / BN, ROWS / BM), 256, GEMM_SMEM>>>(
        X, W, bW, pre_p, NUNI, NUNI, 4 * NH, 4 * NH);

    // ft = sigmoid(F@W1_r + b_r) * tanh(F@W1_d + b_d)  -> permuted rows, fused
    gemm_field_fused<<<dim3(16, ROWS / BM), 256, GEMM_SMEM>>>(F, W1, bW1, ft_p);

    // recurrence: one persistent kernel
    lstm_persistent<<<PBLK, 256, PERS_SMEM>>>(W, len, out);
}

// round 5
// speedup vs baseline: 3.2567x; 1.9584x over previous
#include <cuda_runtime.h>
#include <cuda_fp16.h>
#include <cstdint>
#include <cstddef>

// Problem constants
#define NB   64
#define NS   512
#define NUNI 1024
#define NH   1024
#define NFLD 256
#define ROWS (NB * NS)                       // 32768
#define EMIT_ELEMS ((size_t)NB * NS * NH)    // 33554432

// ---------------- scratch (static __device__: no allocation) ----------------
__device__ float  g_pre[(size_t)ROWS * 4 * NH];   // (t*64+b) x 4096
__device__ float  g_ft [(size_t)ROWS * NH];       // (t*64+b) x 1024
__device__ __half g_hb16[2][NB * NH];             // fp16 h exchange buffers
__device__ unsigned g_arrive_ctr;

// ---------------- helpers ----------------
__device__ __forceinline__ uint32_t f2tf32(float x) {
    uint32_t r;
    asm("cvt.rna.tf32.f32 %0, %1;" : "=r"(r) : "f"(x));
    return r;
}
__device__ __forceinline__ float tf32f(float x) { return __uint_as_float(f2tf32(x)); }

__device__ __forceinline__ void mma_tf32(float d[4], const uint32_t a[4], const uint32_t b[2]) {
    asm volatile(
        "mma.sync.aligned.m16n8k8.row.col.f32.tf32.tf32.f32 "
        "{%0,%1,%2,%3}, {%4,%5,%6,%7}, {%8,%9}, {%0,%1,%2,%3};"
        : "+f"(d[0]), "+f"(d[1]), "+f"(d[2]), "+f"(d[3])
        : "r"(a[0]), "r"(a[1]), "r"(a[2]), "r"(a[3]), "r"(b[0]), "r"(b[1]));
}

__device__ __forceinline__ void mma_f16(float d[4], uint32_t a0, uint32_t a1,
                                        uint32_t a2, uint32_t a3,
                                        uint32_t b0, uint32_t b1) {
    asm volatile(
        "mma.sync.aligned.m16n8k16.row.col.f32.f16.f16.f32 "
        "{%0,%1,%2,%3}, {%4,%5,%6,%7}, {%8,%9}, {%0,%1,%2,%3};"
        : "+f"(d[0]), "+f"(d[1]), "+f"(d[2]), "+f"(d[3])
        : "r"(a0), "r"(a1), "r"(a2), "r"(a3), "r"(b0), "r"(b1));
}

__device__ __forceinline__ uint32_t smem_u32(const void* p) {
    return (uint32_t)__cvta_generic_to_shared(p);
}
__device__ __forceinline__ uint32_t h2u(__half2 h) { return *(uint32_t*)&h; }

__device__ __forceinline__ float sigf(float x) { return 1.0f / (1.0f + expf(-x)); }

// ---------------- init: zero fp16 h buffer + reset barrier ----------------
__global__ void init_kernel() {
    int i = blockIdx.x * blockDim.x + threadIdx.x;
    if (i == 0) g_arrive_ctr = 0u;
    if (i < NB * NH / 2) ((uint32_t*)g_hb16[0])[i] = 0u;
}

// =======================================================================
// fp16 double-buffered GEMM: C = A(MxK fp32)*B(KxN fp32) + bias, fp32 out
// BM=128, BN=128, BK=32, 256 threads (8 warps 4x2), warp tile 32x64.
// Output rows permuted: r=(b*512+t) -> (t*64+b).
// =======================================================================
#define BM 128
#define BN 128
#define BK 32
#define A16_STR 40          // halves per A row (32 + 8 pad)
#define B16_STR 136         // half2 per B k-pair row (128 + 8 pad)
#define A16_BUF (BM * A16_STR)      // 5120 halves
#define B16_BUF (16 * B16_STR)      // 2176 half2
#define GEMM16_SMEM (2 * A16_BUF * 2 + 2 * B16_BUF * 4)   // 37888 B

__global__ __launch_bounds__(256) void gemm_f16_db(
    const float* __restrict__ A, const float* __restrict__ B,
    const float* __restrict__ bias, float* __restrict__ C,
    int K, int lda, int ldb, int ldc)
{
    extern __shared__ char smraw[];
    __half*  As = (__half*)smraw;                       // 2 x 128 x 40 halves
    __half2* Bs = (__half2*)(smraw + 2 * A16_BUF * 2);  // 2 x 16 x 136 half2

    const int tid  = threadIdx.x;
    const int warp = tid >> 5, lane = tid & 31;
    const int wm = warp >> 1, wn = warp & 1;
    const int gid = lane >> 2, kid = lane & 3;
    const int m0 = blockIdx.y * BM;
    const int n0 = blockIdx.x * BN;

    float acc[2][8][4];
    #pragma unroll
    for (int i = 0; i < 2; i++)
        #pragma unroll
        for (int j = 0; j < 8; j++)
            #pragma unroll
            for (int q = 0; q < 4; q++) acc[i][j][q] = 0.0f;

    float4 ar[4], br0[2], br1[2];

    auto load_tile = [&](int kt) {
        #pragma unroll
        for (int i = 0; i < 4; i++) {
            int idx = tid + i * 256;
            int r = idx >> 3, q = idx & 7;
            ar[i] = *(const float4*)(A + (size_t)(m0 + r) * lda + kt + q * 4);
        }
        #pragma unroll
        for (int i = 0; i < 2; i++) {
            int s = tid + i * 256;
            int k2 = s >> 5, cg = s & 31;
            br0[i] = *(const float4*)(B + (size_t)(kt + 2 * k2)     * ldb + n0 + cg * 4);
            br1[i] = *(const float4*)(B + (size_t)(kt + 2 * k2 + 1) * ldb + n0 + cg * 4);
        }
    };
    auto store_tile = [&](int buf) {
        #pragma unroll
        for (int i = 0; i < 4; i++) {
            int idx = tid + i * 256;
            int r = idx >> 3, q = idx & 7;
            uint2 u;
            u.x = h2u(__floats2half2_rn(ar[i].x, ar[i].y));
            u.y = h2u(__floats2half2_rn(ar[i].z, ar[i].w));
            *(uint2*)&As[(size_t)buf * A16_BUF + r * A16_STR + q * 4] = u;
        }
        #pragma unroll
        for (int i = 0; i < 2; i++) {
            int s = tid + i * 256;
            int k2 = s >> 5, cg = s & 31;
            uint4 u;
            u.x = h2u(__floats2half2_rn(br0[i].x, br1[i].x));
            u.y = h2u(__floats2half2_rn(br0[i].y, br1[i].y));
            u.z = h2u(__floats2half2_rn(br0[i].z, br1[i].z));
            u.w = h2u(__floats2half2_rn(br0[i].w, br1[i].w));
            *(uint4*)&Bs[(size_t)buf * B16_BUF + k2 * B16_STR + cg * 4] = u;
        }
    };

    load_tile(0);
    store_tile(0);
    __syncthreads();

    for (int kt = 0; kt < K; kt += BK) {
        const int buf = (kt >> 5) & 1;
        const bool more = (kt + BK) < K;
        if (more) load_tile(kt + BK);

        const __half*  Ac = As + (size_t)buf * A16_BUF;
        const __half2* Bc = Bs + (size_t)buf * B16_BUF;
        #pragma unroll
        for (int kk2 = 0; kk2 < 2; kk2++) {
            uint32_t af[2][4], bf[8][2];
            #pragma unroll
            for (int mi = 0; mi < 2; mi++) {
                int r = wm * 32 + mi * 16 + gid;
                af[mi][0] = *(const uint32_t*)&Ac[r * A16_STR + kk2 * 16 + kid * 2];
                af[mi][1] = *(const uint32_t*)&Ac[(r + 8) * A16_STR + kk2 * 16 + kid * 2];
                af[mi][2] = *(const uint32_t*)&Ac[r * A16_STR + kk2 * 16 + kid * 2 + 8];
                af[mi][3] = *(const uint32_t*)&Ac[(r + 8) * A16_STR + kk2 * 16 + kid * 2 + 8];
            }
            #pragma unroll
            for (int ni = 0; ni < 8; ni++) {
                int cc = wn * 64 + ni * 8 + gid;
                bf[ni][0] = *(const uint32_t*)&Bc[(kk2 * 8 + kid)     * B16_STR + cc];
                bf[ni][1] = *(const uint32_t*)&Bc[(kk2 * 8 + kid + 4) * B16_STR + cc];
            }
            #pragma unroll
            for (int mi = 0; mi < 2; mi++)
                #pragma unroll
                for (int ni = 0; ni < 8; ni++)
                    mma_f16(acc[mi][ni], af[mi][0], af[mi][1], af[mi][2], af[mi][3],
                            bf[ni][0], bf[ni][1]);
        }
        if (more) store_tile(buf ^ 1);
        __syncthreads();
    }

    // Epilogue: bias + permuted store  (row b*512+t -> t*64+b)
    #pragma unroll
    for (int mi = 0; mi < 2; mi++) {
        int r = m0 + wm * 32 + mi * 16 + gid;
        int r0 = (r & (NS - 1)) * NB + (r >> 9);
        int r1 = ((r + 8) & (NS - 1)) * NB + ((r + 8) >> 9);
        #pragma unroll
        for (int ni = 0; ni < 8; ni++) {
            int cc = n0 + wn * 64 + ni * 8 + 2 * kid;
            float b0 = bias[cc], b1 = bias[cc + 1];
            C[(size_t)r0 * ldc + cc]     = acc[mi][ni][0] + b0;
            C[(size_t)r0 * ldc + cc + 1] = acc[mi][ni][1] + b1;
            C[(size_t)r1 * ldc + cc]     = acc[mi][ni][2] + b0;
            C[(size_t)r1 * ldc + cc + 1] = acc[mi][ni][3] + b1;
        }
    }
}

// =======================================================================
// fused field GEMM (tf32, unchanged from R3): ft = sig(F@W1r+br)*tanh(F@W1d+bd)
// =======================================================================
#define AS_STR 36
#define BS_STR 136
#define GEMM_SMEM ((2 * BM * AS_STR + 2 * BK * BS_STR) * 4)   // 71680 B

__device__ __forceinline__ void gemm_stage_store(
    float* As, float* Bs, int buf, const float4* ar, const float4* br, int tid)
{
    #pragma unroll
    for (int i = 0; i < 4; i++) {
        int idx = tid + i * 256;
        int r = idx >> 3, q = idx & 7;
        float4 v = ar[i];
        float4 cv = make_float4(tf32f(v.x), tf32f(v.y), tf32f(v.z), tf32f(v.w));
        *(float4*)&As[(size_t)buf * BM * AS_STR + r * AS_STR + q * 4] = cv;
    }
    #pragma unroll
    for (int i = 0; i < 4; i++) {
        int idx = tid + i * 256;
        int r = idx >> 5, q = idx & 31;
        float4 v = br[i];
        float4 cv = make_float4(tf32f(v.x), tf32f(v.y), tf32f(v.z), tf32f(v.w));
        *(float4*)&Bs[(size_t)buf * BK * BS_STR + r * BS_STR + q * 4] = cv;
    }
}

__global__ __launch_bounds__(256) void gemm_field_fused(
    const float* __restrict__ A, const float* __restrict__ B,
    const float* __restrict__ bias, float* __restrict__ C)
{
    extern __shared__ float sm[];
    float* As = sm;
    float* Bs = sm + 2 * BM * AS_STR;
    float* Ds = sm;

    const int tid  = threadIdx.x;
    const int warp = tid >> 5, lane = tid & 31;
    const int wm = warp >> 1, wn = warp & 1;
    const int gid = lane >> 2, kid = lane & 3;
    const int m0 = blockIdx.y * BM;
    const int n0 = blockIdx.x * 64;
    const int K = NFLD, lda = NFLD, ldb = 2 * NH;

    float acc[2][8][4];
    #pragma unroll
    for (int i = 0; i < 2; i++)
        #pragma unroll
        for (int j = 0; j < 8; j++)
            #pragma unroll
            for (int q = 0; q < 4; q++) acc[i][j][q] = 0.0f;

    float4 ar[4], br[4];
    #pragma unroll
    for (int i = 0; i < 4; i++) {
        int idx = tid + i * 256;
        int r = idx >> 3, q = idx & 7;
        ar[i] = *(const float4*)(A + (size_t)(m0 + r) * lda + q * 4);
    }
    #pragma unroll
    for (int i = 0; i < 4; i++) {
        int idx = tid + i * 256;
        int r = idx >> 5, q = idx & 31;
        int col = (q < 16) ? (n0 + q * 4) : (NH + n0 + (q - 16) * 4);
        br[i] = *(const float4*)(B + (size_t)r * ldb + col);
    }
    gemm_stage_store(As, Bs, 0, ar, br, tid);
    __syncthreads();

    for (int kt = 0; kt < K; kt += BK) {
        const int buf = (kt >> 5) & 1;
        const bool more = (kt + BK) < K;
        if (more) {
            #pragma unroll
            for (int i = 0; i < 4; i++) {
                int idx = tid + i * 256;
                int r = idx >> 3, q = idx & 7;
                ar[i] = *(const float4*)(A + (size_t)(m0 + r) * lda + kt + BK + q * 4);
            }
            #pragma unroll
            for (int i = 0; i < 4; i++) {
                int idx = tid + i * 256;
                int r = idx >> 5, q = idx & 31;
                int col = (q < 16) ? (n0 + q * 4) : (NH + n0 + (q - 16) * 4);
                br[i] = *(const float4*)(B + (size_t)(kt + BK + r) * ldb + col);
            }
        }
        const float* Ac = As + (size_t)buf * BM * AS_STR;
        const float* Bc = Bs + (size_t)buf * BK * BS_STR;
        #pragma unroll
        for (int kk = 0; kk < BK; kk += 8) {
            uint32_t af[2][4], bf[8][2];
            #pragma unroll
            for (int mi = 0; mi < 2; mi++) {
                int r = wm * 32 + mi * 16 + gid;
                af[mi][0] = __float_as_uint(Ac[r * AS_STR + kk + kid]);
                af[mi][1] = __float_as_uint(Ac[(r + 8) * AS_STR + kk + kid]);
                af[mi][2] = __float_as_uint(Ac[r * AS_STR + kk + kid + 4]);
                af[mi][3] = __float_as_uint(Ac[(r + 8) * AS_STR + kk + kid + 4]);
            }
            #pragma unroll
            for (int ni = 0; ni < 8; ni++) {
                int cc = wn * 64 + ni * 8 + gid;
                bf[ni][0] = __float_as_uint(Bc[(kk + kid) * BS_STR + cc]);
                bf[ni][1] = __float_as_uint(Bc[(kk + kid + 4) * BS_STR + cc]);
            }
            #pragma unroll
            for (int mi = 0; mi < 2; mi++)
                #pragma unroll
                for (int ni = 0; ni < 8; ni++)
                    mma_tf32(acc[mi][ni], af[mi], bf[ni]);
        }
        __syncthreads();
        if (more) { gemm_stage_store(As, Bs, buf ^ 1, ar, br, tid); __syncthreads(); }
    }

    if (wn == 1) {
        #pragma unroll
        for (int mi = 0; mi < 2; mi++) {
            int lr = wm * 32 + mi * 16 + gid;
            #pragma unroll
            for (int ni = 0; ni < 8; ni++) {
                int cc = ni * 8 + 2 * kid;
                float b0 = bias[NH + n0 + cc], b1 = bias[NH + n0 + cc + 1];
                Ds[lr * 68 + cc]           = acc[mi][ni][0] + b0;
                Ds[lr * 68 + cc + 1]       = acc[mi][ni][1] + b1;
                Ds[(lr + 8) * 68 + cc]     = acc[mi][ni][2] + b0;
                Ds[(lr + 8) * 68 + cc + 1] = acc[mi][ni][3] + b1;
            }
        }
    }
    __syncthreads();
    if (wn == 0) {
        #pragma unroll
        for (int mi = 0; mi < 2; mi++) {
            int lr = wm * 32 + mi * 16 + gid;
            int r = m0 + lr;
            int r0 = (r & (NS - 1)) * NB + (r >> 9);
            int r1 = ((r + 8) & (NS - 1)) * NB + ((r + 8) >> 9);
            #pragma unroll
            for (int ni = 0; ni < 8; ni++) {
                int cc = ni * 8 + 2 * kid;
                float b0 = bias[n0 + cc], b1 = bias[n0 + cc + 1];
                float2 o0, o1;
                o0.x = sigf(acc[mi][ni][0] + b0) * tanhf(Ds[lr * 68 + cc]);
                o0.y = sigf(acc[mi][ni][1] + b1) * tanhf(Ds[lr * 68 + cc + 1]);
                o1.x = sigf(acc[mi][ni][2] + b0) * tanhf(Ds[(lr + 8) * 68 + cc]);
                o1.y = sigf(acc[mi][ni][3] + b1) * tanhf(Ds[(lr + 8) * 68 + cc + 1]);
                *(float2*)(C + (size_t)r0 * NH + n0 + cc) = o0;
                *(float2*)(C + (size_t)r1 * NH + n0 + cc) = o1;
            }
        }
    }
}

// =======================================================================
// persistent fp16 LSTM recurrence
// 128 blocks x 256 threads. Block owns 8 h-cols (32 gate cols).
// Wh pre-packed into mma B-fragment order in SMEM (fp16, 64KB).
// h exchanged fp16 via global double buffer, staged with cp.async;
// A-fragments via ldmatrix.x4. c/h cell state in registers.
// =======================================================================
#define PBLK 128
#define KC 128
#define RS 136                                   // halves per staged A row
#define CHUNK_BYTES (64 * RS * 2)                // 17408
#define WHF_HALVES (8 * 8 * 2 * 32 * 8)          // 32768 halves = 64KB
#define PERS_SMEM (WHF_HALVES * 2 + 2 * CHUNK_BYTES)   // 100352 B

__global__ __launch_bounds__(256) void lstm_persistent(
    const float* __restrict__ W, const int* __restrict__ len, float* __restrict__ out)
{
    extern __shared__ __half smh[];
    __half* Whf   = smh;                          // fragment-ordered Wh
    __half* Asb16 = smh + WHF_HALVES;             // 2 x 64 x 136 halves
    float*  Gs    = (float*)Asb16;                // epilogue alias
    __shared__ int lens[NB];

    const int tid  = threadIdx.x;
    const int warp = tid >> 5, lane = tid & 31;
    const int wm = warp >> 1, wg = warp & 1;
    const int gid = lane >> 2, kid = lane & 3;
    const int hbase = blockIdx.x * 8;
    const float* Wh = W + (size_t)1024 * 4096;
    const uint4* Whf4 = (const uint4*)Whf;

    // ---- init: pack Wh fragments (fp16) ----
    for (int item = tid; item < 4096; item += 256) {
        int ln = item & 31, wgi = (item >> 5) & 1, g = (item >> 6) & 7, ci = item >> 9;
        int t4 = ln & 3, gi = ln >> 2;
        int kbase = ci * 128 + g * 16 + t4 * 2;
        __half hv[8];
        #pragma unroll
        for (int ni = 0; ni < 2; ni++) {
            int cc = wgi * 16 + ni * 8 + gi;
            int gcol = (cc >> 3) * 1024 + hbase + (cc & 7);
            hv[ni * 4 + 0] = __float2half(Wh[(size_t)(kbase + 0) * 4096 + gcol]);
            hv[ni * 4 + 1] = __float2half(Wh[(size_t)(kbase + 1) * 4096 + gcol]);
            hv[ni * 4 + 2] = __float2half(Wh[(size_t)(kbase + 8) * 4096 + gcol]);
            hv[ni * 4 + 3] = __float2half(Wh[(size_t)(kbase + 9) * 4096 + gcol]);
        }
        *(uint4*)&Whf[(size_t)item * 8] = *(uint4*)hv;
    }
    if (tid < NB) lens[tid] = len[tid];
    __syncthreads();

    const int eb  = tid >> 2;
    const int ehc = (tid & 3) * 2;
    const int mylen = lens[eb];
    const int hcol  = hbase + ehc;
    float2 creg = make_float2(0.f, 0.f);
    float2 hreg = make_float2(0.f, 0.f);

    const uint32_t asb = smem_u32(Asb16);
    // ldmatrix per-thread address base: rows wm*16 + (lane&15), koff (lane>>4)*8
    const uint32_t aBase0 = asb + (((wm * 16 + (lane & 15)) * RS + (lane >> 4) * 8) * 2);

    // epilogue operand prefetch for t=0
    float2 pg0, pg1, pg2, pg3, ftv;
    {
        size_t prow = (size_t)0 * NB + eb;
        pg0 = *(const float2*)(g_pre + prow * 4096 +        hcol);
        pg1 = *(const float2*)(g_pre + prow * 4096 + 1024 + hcol);
        pg2 = *(const float2*)(g_pre + prow * 4096 + 2048 + hcol);
        pg3 = *(const float2*)(g_pre + prow * 4096 + 3072 + hcol);
        ftv = *(const float2*)(g_ft  + prow * 1024 +        hcol);
    }

    for (int t = 0; t < NS; t++) {
        const __half* hr16 = g_hb16[t & 1];
        __half*       hw16 = g_hb16[(t & 1) ^ 1];

        float acc[2][4] = {{0.f,0.f,0.f,0.f},{0.f,0.f,0.f,0.f}};

        // issue chunk ci via cp.async (4 x 16B per thread)
        auto issue = [&](int ci) {
            int kn = ci * KC, buf = ci & 1;
            #pragma unroll
            for (int j = 0; j < 4; j++) {
                int s = tid + j * 256;
                int row = s >> 4, q = s & 15;
                uint32_t dst = asb + buf * CHUNK_BYTES + (row * RS + q * 8) * 2;
                const __half* src = hr16 + (size_t)row * NH + kn + q * 8;
                asm volatile("cp.async.cg.shared.global [%0], [%1], 16;"
                             :: "r"(dst), "l"(src));
            }
            asm volatile("cp.async.commit_group;");
        };

        issue(0);
        #pragma unroll 1
        for (int ci = 0; ci < 8; ci++) {
            if (ci < 7) {
                issue(ci + 1);
                asm volatile("cp.async.wait_group 1;");
            } else {
                asm volatile("cp.async.wait_group 0;");
            }
            __syncthreads();

            const uint32_t aB = aBase0 + (ci & 1) * CHUNK_BYTES;
            #pragma unroll
            for (int g = 0; g < 8; g++) {
                uint32_t a0, a1, a2, a3;
                asm volatile(
                    "ldmatrix.sync.aligned.m8n8.x4.shared.b16 {%0,%1,%2,%3}, [%4];"
                    : "=r"(a0), "=r"(a1), "=r"(a2), "=r"(a3)
                    : "r"(aB + g * 32));
                uint4 bv = Whf4[(((ci << 3) + g) * 2 + wg) * 32 + lane];
                mma_f16(acc[0], a0, a1, a2, a3, bv.x, bv.y);
                mma_f16(acc[1], a0, a1, a2, a3, bv.z, bv.w);
            }
            __syncthreads();
        }

        // gate exchange (Gs aliases A buffers — free after last sync)
        {
            int rr = wm * 16 + gid;
            #pragma unroll
            for (int ni = 0; ni < 2; ni++) {
                int cc = wg * 16 + ni * 8 + 2 * kid;
                Gs[rr * 36 + cc]           = acc[ni][0];
                Gs[rr * 36 + cc + 1]       = acc[ni][1];
                Gs[(rr + 8) * 36 + cc]     = acc[ni][2];
                Gs[(rr + 8) * 36 + cc + 1] = acc[ni][3];
            }
        }
        __syncthreads();

        // cell update (2 cells per thread)
        bool act = (t < mylen);
        float gi0 = Gs[eb * 36 + ehc]      + pg0.x;
        float gj0 = Gs[eb * 36 + 8 + ehc]  + pg1.x;
        float gf0 = Gs[eb * 36 + 16 + ehc] + pg2.x;
        float go0 = Gs[eb * 36 + 24 + ehc] + pg3.x;
        float gi1 = Gs[eb * 36 + ehc + 1]      + pg0.y;
        float gj1 = Gs[eb * 36 + 8 + ehc + 1]  + pg1.y;
        float gf1 = Gs[eb * 36 + 16 + ehc + 1] + pg2.y;
        float go1 = Gs[eb * 36 + 24 + ehc + 1] + pg3.y;

        float cn0 = sigf(gf0 + 1.0f) * creg.x + sigf(gi0) * tanhf(gj0) + ftv.x;
        float hn0 = sigf(go0) * tanhf(cn0);
        float cn1 = sigf(gf1 + 1.0f) * creg.y + sigf(gi1) * tanhf(gj1) + ftv.y;
        float hn1 = sigf(go1) * tanhf(cn1);

        float2 emit = make_float2(act ? hn0 : 0.0f, act ? hn1 : 0.0f);
        creg.x = act ? cn0 : creg.x;  creg.y = act ? cn1 : creg.y;
        hreg.x = act ? hn0 : hreg.x;  hreg.y = act ? hn1 : hreg.y;

        // fp16 h must be visible before barrier arrive
        *(__half2*)(hw16 + (size_t)eb * NH + hcol) = __floats2half2_rn(hreg.x, hreg.y);
        __threadfence();
        __syncthreads();

        if (t < NS - 1) {
            if (tid == 0) {
                unsigned prev;
                asm volatile("atom.add.release.gpu.u32 %0, [%1], %2;"
                             : "=r"(prev) : "l"(&g_arrive_ctr), "r"(1u) : "memory");
            }
            // off critical path: emit store + next-step operand prefetch
            *(float2*)(out + ((size_t)eb * NS + t) * NH + hcol) = emit;
            {
                size_t prow = (size_t)(t + 1) * NB + eb;
                pg0 = *(const float2*)(g_pre + prow * 4096 +        hcol);
                pg1 = *(const float2*)(g_pre + prow * 4096 + 1024 + hcol);
                pg2 = *(const float2*)(g_pre + prow * 4096 + 2048 + hcol);
                pg3 = *(const float2*)(g_pre + prow * 4096 + 3072 + hcol);
                ftv = *(const float2*)(g_ft  + prow * 1024 +        hcol);
            }
            if (tid == 0) {
                unsigned target = (unsigned)(PBLK * (t + 1)), v;
                do {
                    asm volatile("ld.acquire.gpu.u32 %0, [%1];"
                                 : "=r"(v) : "l"(&g_arrive_ctr) : "memory");
                } while (v < target);
            }
            __syncthreads();
        } else {
            *(float2*)(out + ((size_t)eb * NS + t) * NH + hcol) = emit;
        }
    }

    // finals (fp32 from registers)
    *(float2*)(out + EMIT_ELEMS + (size_t)eb * NH + hcol)           = hreg;
    *(float2*)(out + EMIT_ELEMS + NB * NH + (size_t)eb * NH + hcol) = creg;
}

// ---------------- host ----------------
extern "C" void kernel_launch(void* const* d_in, const int* in_sizes, int n_in,
                              void* d_out, int out_size)
{
    const float* X   = (const float*)d_in[0];  // (64, 512, 1024)
    const float* F   = (const float*)d_in[1];  // (64, 512, 256)
    const int*   len = (const int*)  d_in[2];  // (64,)
    const float* W   = (const float*)d_in[3];  // (2048, 4096)
    const float* bW  = (const float*)d_in[4];  // (4096,)
    const float* W1  = (const float*)d_in[5];  // (256, 2048)
    const float* bW1 = (const float*)d_in[6];  // (2048,)
    float* out = (float*)d_out;

    float *pre_p, *ft_p;
    cudaGetSymbolAddress((void**)&pre_p, g_pre);
    cudaGetSymbolAddress((void**)&ft_p,  g_ft);

    static bool attrs_set = false;
    if (!attrs_set) {
        cudaFuncSetAttribute(gemm_f16_db,
                             cudaFuncAttributeMaxDynamicSharedMemorySize, GEMM16_SMEM);
        cudaFuncSetAttribute(gemm_field_fused,
                             cudaFuncAttributeMaxDynamicSharedMemorySize, GEMM_SMEM);
        cudaFuncSetAttribute(lstm_persistent,
                             cudaFuncAttributeMaxDynamicSharedMemorySize, PERS_SMEM);
        attrs_set = true;
    }

    // reset barrier + zero fp16 h buffer
    init_kernel<<<256, 256>>>();

    // pre = X @ W[0:1024,:] + bW  -> permuted rows (t*64+b)   [fp16 tensor cores]
    gemm_f16_db<<<dim3(4 * NH / BN, ROWS / BM), 256, GEMM16_SMEM>>>(
        X, W, bW, pre_p, NUNI, NUNI, 4 * NH, 4 * NH);

    // ft = sigmoid(F@W1_r + b_r) * tanh(F@W1_d + b_d)  -> permuted rows (tf32)
    gemm_field_fused<<<dim3(16, ROWS / BM), 256, GEMM_SMEM>>>(F, W1, bW1, ft_p);

    // recurrence: one persistent fp16 kernel
    lstm_persistent<<<PBLK, 256, PERS_SMEM>>>(W, len, out);
}